// round 4
// baseline (speedup 1.0000x reference)
#include <cuda_runtime.h>
#include <cstddef>

#define HH   8
#define TQ   2048
#define TT   4096
#define DK   64
#define NB   64
#define NQG    (HH*TQ)     // 16384
#define NUNITS (HH*NB)     // 512
#define GRID_P 444         // 3 CTAs/SM x 148 SMs

typedef unsigned long long ull;

// Merged flash accumulators (m == 0 for every partial, so slots add):
//   g_oacc[q*64 + d] = sum over both selected blocks of exp(s)*V
//   g_lsum[q]        = sum of exp(s)
// Zero-initialized at load; normalize_kernel re-zeros after reading.
__device__ float g_oacc[(size_t)NQG * DK];
__device__ float g_lsum[NQG];
__device__ int   g_ticket = GRID_P;

#define FMA2(d,a,b,c) asm("fma.rn.f32x2 %0, %1, %2, %3;" : "=l"(d) : "l"(a), "l"(b), "l"(c))
#define ADD2(d,a,b)   asm("add.rn.f32x2 %0, %1, %2;"     : "=l"(d) : "l"(a), "l"(b))

// ---- dynamic SMEM layout (float offsets) ----
#define KS_OFF    0        // K block: 64 rows x 68 floats (pad -> conflict-free)
#define VS_OFF    4352     // V block: same
#define UBUF_OFF  8704     // per-warp 1024 floats: phase1 q rows, phase2 dup'd P
#define QLIST_OFF 16896    // 2048 ushort
#define NM_OFF    17920    // nmatch, nextu
#define SMEM_BYTES ((NM_OFF + 4) * 4)   // 71696

__global__ __launch_bounds__(256, 3)
void partial_kernel(const float* __restrict__ q,
                    const float* __restrict__ k,
                    const float* __restrict__ v,
                    const int*   __restrict__ idx)
{
    extern __shared__ float sm[];
    float* ks = sm + KS_OFF;
    float* vs = sm + VS_OFF;
    unsigned short* qlist = (unsigned short*)(sm + QLIST_OFF);
    int* nmatch = (int*)(sm + NM_OFF);
    int* nextu  = nmatch + 1;

    const int tid  = threadIdx.x;
    const int warp = tid >> 5;
    const int lane = tid & 31;
    float* ubuf = sm + UBUF_OFF + warp * 1024;

    int u = blockIdx.x;
    while (u < NUNITS) {
        const int hh = u >> 6, bl = u & 63;
        if (tid == 0) *nmatch = 0;

        // ---- stage K/V block (64x64 f32) into padded SMEM ----
        const float4* kg = (const float4*)(k + ((size_t)hh * TT + (size_t)bl * 64) * DK);
        const float4* vg = (const float4*)(v + ((size_t)hh * TT + (size_t)bl * 64) * DK);
        float4* ks4 = (float4*)ks;
        float4* vs4 = (float4*)vs;
        #pragma unroll
        for (int i = tid; i < 1024; i += 256) {
            int row = i >> 4, c = i & 15;
            ks4[row * 17 + c] = kg[i];
            vs4[row * 17 + c] = vg[i];
        }
        __syncthreads();

        // ---- scan top2 list; warp-aggregated append ----
        const int2* idxh = (const int2*)(idx + (size_t)hh * TQ * 2);
        #pragma unroll
        for (int qq = tid; qq < TQ; qq += 256) {
            int2 t2 = idxh[qq];
            int mk = (t2.x == bl ? 1 : 0) | (t2.y == bl ? 2 : 0);
            unsigned bal = __ballot_sync(0xFFFFFFFFu, mk != 0);
            if (mk) {
                int leader = __ffs(bal) - 1;
                int base;
                if (lane == leader) base = atomicAdd(nmatch, __popc(bal));
                base = __shfl_sync(bal, base, leader);
                int pos = base + __popc(bal & ((1u << lane) - 1u));
                qlist[pos] = (unsigned short)(qq | (mk << 12));
            }
        }
        __syncthreads();
        const int n = *nmatch;

        // ---- warp-tiles of 8 queries ----
        for (int base = warp * 8; base < n; base += 64) {
            const int nt = min(8, n - base);
            int qgr[8], mkr[8];
            #pragma unroll
            for (int r = 0; r < 8; r++) {
                int e = base + ((r < nt) ? r : 0);
                unsigned short ent = qlist[e];
                qgr[r] = hh * TQ + (ent & 0x0FFF);
                mkr[r] = (r < nt) ? (ent >> 12) : 0;
            }

            __syncwarp();   // prior tile's ubuf reads done
            #pragma unroll
            for (int r = 0; r < 8; r++) {
                float2 qv = ((const float2*)(q + (size_t)qgr[r] * DK))[lane];
                ((float2*)(ubuf + r * 64))[lane] = qv;
            }
            __syncwarp();

            // ---- QK: lane owns keys {lane, lane+32}; f32x2 along dk ----
            ull sA[8], sB[8];
            #pragma unroll
            for (int r = 0; r < 8; r++) { sA[r] = 0ull; sB[r] = 0ull; }
            {
                const ulonglong2* ka4 = (const ulonglong2*)(ks + lane * 68);
                const ulonglong2* kb4 = (const ulonglong2*)(ks + (lane + 32) * 68);
                #pragma unroll
                for (int i = 0; i < 16; i++) {
                    ulonglong2 ka = ka4[i];
                    ulonglong2 kb = kb4[i];
                    #pragma unroll
                    for (int r = 0; r < 8; r++) {
                        ulonglong2 qv = ((const ulonglong2*)(ubuf + r * 64))[i];
                        FMA2(sA[r], qv.x, ka.x, sA[r]);
                        FMA2(sA[r], qv.y, ka.y, sA[r]);
                        FMA2(sB[r], qv.x, kb.x, sB[r]);
                        FMA2(sB[r], qv.y, kb.y, sB[r]);
                    }
                }
            }
            __syncwarp();   // q reads done before P overwrites ubuf

            // ---- exp (no max shift: scores are O(1), fp32-safe) ----
            // l-sum reduced and RED'd immediately; dup'd (p,p) stored for PV.
            #pragma unroll
            for (int r = 0; r < 8; r++) {
                unsigned lo, hi;
                asm("mov.b64 {%0,%1}, %2;" : "=r"(lo), "=r"(hi) : "l"(sA[r]));
                float s0 = (__uint_as_float(lo) + __uint_as_float(hi)) * 0.125f;
                asm("mov.b64 {%0,%1}, %2;" : "=r"(lo), "=r"(hi) : "l"(sB[r]));
                float s1 = (__uint_as_float(lo) + __uint_as_float(hi)) * 0.125f;
                float e0 = __expf(s0), e1 = __expf(s1);
                float l = e0 + e1;
                #pragma unroll
                for (int o = 16; o; o >>= 1) l += __shfl_xor_sync(0xFFFFFFFFu, l, o);
                ull d0, d1;
                unsigned e0u = __float_as_uint(e0), e1u = __float_as_uint(e1);
                asm("mov.b64 %0, {%1,%1};" : "=l"(d0) : "r"(e0u));
                asm("mov.b64 %0, {%1,%1};" : "=l"(d1) : "r"(e1u));
                ((ull*)ubuf)[r * 64 + lane]      = d0;
                ((ull*)ubuf)[r * 64 + lane + 32] = d1;
                if (lane == 0 && mkr[r]) {
                    float lc = (mkr[r] == 3) ? (l + l) : l;   // dup-block weight
                    asm volatile("red.global.add.f32 [%0], %1;"
                                 :: "l"(g_lsum + qgr[r]), "f"(lc) : "memory");
                }
            }
            __syncwarp();

            // ---- PV: lane owns dims {2*lane, 2*lane+1} ----
            ull acc[8];
            #pragma unroll
            for (int r = 0; r < 8; r++) acc[r] = 0ull;
            {
                const ull* vr = (const ull*)vs;
                const ull* pb = (const ull*)ubuf;
                #pragma unroll 8
                for (int j = 0; j < 64; j++) {
                    ull v2 = vr[j * 34 + lane];
                    #pragma unroll
                    for (int r = 0; r < 8; r++)
                        FMA2(acc[r], pb[r * 64 + j], v2, acc[r]);
                }
            }

            // ---- RED-accumulate into merged output buffer ----
            #pragma unroll
            for (int r = 0; r < 8; r++) {
                if (mkr[r]) {
                    ull a = acc[r];
                    if (mkr[r] == 3) ADD2(a, a, a);           // x2 for dup block
                    unsigned alo, ahi;
                    asm("mov.b64 {%0,%1}, %2;" : "=r"(alo), "=r"(ahi) : "l"(a));
                    float* dst = g_oacc + (size_t)qgr[r] * DK + 2 * lane;
                    asm volatile("red.global.add.v2.f32 [%0], {%1, %2};"
                                 :: "l"(dst), "r"(alo), "r"(ahi) : "memory");
                }
            }
        }

        // ---- steal next unit ----
        if (tid == 0) *nextu = atomicAdd(&g_ticket, 1);
        __syncthreads();
        u = *nextu;
    }
}

// ---------------------------------------------------------------------------
// Normalize: out = oacc / lsum, then re-zero scratch for the next replay.
// ---------------------------------------------------------------------------
__global__ __launch_bounds__(256)
void normalize_kernel(float* __restrict__ out)
{
    const int t  = blockIdx.x * 256 + threadIdx.x;
    if (t == 0) g_ticket = GRID_P;
    const int qg = t >> 4;
    float  ls = g_lsum[qg];
    float4 a  = ((const float4*)g_oacc)[t];
    __syncwarp();                         // all reads of lsum before the zeroing
    const float inv = 1.0f / ls;
    float4 o;
    o.x = a.x * inv;  o.y = a.y * inv;  o.z = a.z * inv;  o.w = a.w * inv;
    ((float4*)out)[t] = o;
    ((float4*)g_oacc)[t] = make_float4(0.f, 0.f, 0.f, 0.f);
    if ((t & 15) == 0) g_lsum[qg] = 0.f;
}

// ---------------------------------------------------------------------------
extern "C" void kernel_launch(void* const* d_in, const int* in_sizes, int n_in,
                              void* d_out, int out_size)
{
    const float* q = nullptr; const float* k = nullptr; const float* v = nullptr;
    const int* idx = nullptr;
    for (int i = 0; i < n_in; i++) {
        const int s = in_sizes[i];
        if (s == HH * TQ * DK && !q)  q = (const float*)d_in[i];       // 1,048,576
        else if (s == HH * TT * DK) {                                   // 2,097,152
            if (!k) k = (const float*)d_in[i];
            else if (!v) v = (const float*)d_in[i];
        }
        else if (s == HH * TQ * 2)    idx = (const int*)d_in[i];        // 32,768
    }

    cudaFuncSetAttribute(partial_kernel,
                         cudaFuncAttributeMaxDynamicSharedMemorySize, SMEM_BYTES);
    partial_kernel<<<GRID_P, 256, SMEM_BYTES>>>(q, k, v, idx);
    normalize_kernel<<<(NQG * DK / 4) / 256, 256>>>((float*)d_out);
}